// round 1
// baseline (speedup 1.0000x reference)
#include <cuda_runtime.h>
#include <cstdint>
#include <cstddef>

#define NB 64
#define NS 256
#define NH 768
#define NT 13
#define ND 64
#define NN (NT * 2 * ND)   // 1664
#define NEGC 1000000000000.0f

// ---------------- scratch (device globals; no allocation allowed) ----------------
__device__ float  g_x[(size_t)NB * NS * NH];       // tf32-rounded hidden (50.3 MB)
__device__ float  g_w[(size_t)NH * NN];            // tf32-rounded weights (5.1 MB)
__device__ float  g_q[(size_t)NB * NT * NS * ND];  // rotated q, [B][T][S][D] (54.5 MB)
__device__ float  g_k[(size_t)NB * NT * NS * ND];  // rotated k, [B][T][S][D] (54.5 MB)
__device__ float2 g_rope[NS * 32];                 // (cos, sin) per (pos, pair)

// ---------------- helpers ----------------
__device__ __forceinline__ float tf32r(float x) {
    uint32_t u;
    asm("cvt.rna.tf32.f32 %0, %1;" : "=r"(u) : "f"(x));
    return __uint_as_float(u);
}

__device__ __forceinline__ void cpa16(void* dst, const void* src) {
    uint32_t s = (uint32_t)__cvta_generic_to_shared(dst);
    asm volatile("cp.async.cg.shared.global [%0], [%1], 16;" :: "r"(s), "l"(src));
}
#define CP_COMMIT asm volatile("cp.async.commit_group;")
#define CP_WAIT1  asm volatile("cp.async.wait_group 1;")

__device__ __forceinline__ void mma8(float* c, const uint32_t* a, const uint32_t* b) {
    asm volatile(
        "mma.sync.aligned.m16n8k8.row.col.f32.tf32.tf32.f32 "
        "{%0,%1,%2,%3},{%4,%5,%6,%7},{%8,%9},{%0,%1,%2,%3};"
        : "+f"(c[0]), "+f"(c[1]), "+f"(c[2]), "+f"(c[3])
        : "r"(a[0]), "r"(a[1]), "r"(a[2]), "r"(a[3]), "r"(b[0]), "r"(b[1]));
}

// ---------------- prep kernels ----------------
__global__ void k_rope_tab() {
    int idx = blockIdx.x * blockDim.x + threadIdx.x;
    if (idx < NS * 32) {
        int s = idx >> 5, i = idx & 31;
        // inv = 10000^(-2i/64) = exp(-i * ln(10000)/32)
        float inv = expf(-0.28782313662425574f * (float)i);
        float ang = (float)s * inv;
        g_rope[idx] = make_float2(cosf(ang), sinf(ang));
    }
}

__global__ void k_cvt_x(const float* __restrict__ in) {
    size_t i = (size_t)blockIdx.x * blockDim.x + threadIdx.x;
    size_t n4 = (size_t)NB * NS * NH / 4;
    if (i < n4) {
        float4 v = ((const float4*)in)[i];
        v.x = tf32r(v.x); v.y = tf32r(v.y); v.z = tf32r(v.z); v.w = tf32r(v.w);
        ((float4*)g_x)[i] = v;
    }
}

__global__ void k_cvt_w(const float* __restrict__ in) {
    size_t i = (size_t)blockIdx.x * blockDim.x + threadIdx.x;
    size_t n4 = (size_t)NH * NN / 4;
    if (i < n4) {
        float4 v = ((const float4*)in)[i];
        v.x = tf32r(v.x); v.y = tf32r(v.y); v.z = tf32r(v.z); v.w = tf32r(v.w);
        ((float4*)g_w)[i] = v;
    }
}

// ---------------- kernel 1: X@W + bias, fused RoPE, write q/k ----------------
// Tiles: BM=128, BN=128, BK=32. 256 threads = 8 warps (4 rows x 2 cols),
// warp tile 32x64 via mma.m16n8k8 (2 m-tiles x 8 n-tiles).
// As: [128][36] (pad 4 -> conflict-free A-frag reads, 16B-aligned rows)
// Bs: [32][136] (pad 8 -> conflict-free B-frag reads)
#define SMA (128 * 36)
#define SMB (32 * 136)
#define SMEM1 ((2 * SMA + 2 * SMB) * 4)

__global__ __launch_bounds__(256) void k_gemm1(const float* __restrict__ bias) {
    extern __shared__ float sm[];
    float* const As = sm;             // 2 stages
    float* const Bs = sm + 2 * SMA;   // 2 stages

    const int tid  = threadIdx.x;
    const int lane = tid & 31;
    const int warp = tid >> 5;
    const int g    = lane >> 2;
    const int tg   = lane & 3;
    const int wr   = warp & 3;
    const int wc   = warp >> 2;
    const int bM   = blockIdx.y << 7;
    const int bN   = blockIdx.x << 7;

    const int arow = tid >> 3;         // 0..31
    const int acol = (tid & 7) << 2;   // 0,4,..28
    const int brow = tid >> 5;         // 0..7
    const int bcol = (tid & 31) << 2;  // 0,4,..124

    float acc[2][8][4];
#pragma unroll
    for (int i = 0; i < 2; i++)
#pragma unroll
        for (int j = 0; j < 8; j++)
#pragma unroll
            for (int l = 0; l < 4; l++) acc[i][j][l] = 0.f;

    // prologue: stage 0 <- kt 0
    {
#pragma unroll
        for (int i = 0; i < 4; i++) {
            int r = arow + i * 32;
            cpa16(As + r * 36 + acol, g_x + (size_t)(bM + r) * NH + acol);
        }
#pragma unroll
        for (int i = 0; i < 4; i++) {
            int r = brow + i * 8;
            cpa16(Bs + r * 136 + bcol, g_w + (size_t)r * NN + bN + bcol);
        }
        CP_COMMIT;
    }

    for (int kt = 0; kt < 24; kt++) {
        if (kt < 23) {
            const int st = (kt + 1) & 1;
            const int k0 = (kt + 1) << 5;
            float* A  = As + st * SMA;
            float* Bp = Bs + st * SMB;
#pragma unroll
            for (int i = 0; i < 4; i++) {
                int r = arow + i * 32;
                cpa16(A + r * 36 + acol, g_x + (size_t)(bM + r) * NH + k0 + acol);
            }
#pragma unroll
            for (int i = 0; i < 4; i++) {
                int r = brow + i * 8;
                cpa16(Bp + r * 136 + bcol, g_w + (size_t)(k0 + r) * NN + bN + bcol);
            }
        }
        CP_COMMIT;
        CP_WAIT1;
        __syncthreads();

        const float* A  = As + (kt & 1) * SMA;
        const float* Bp = Bs + (kt & 1) * SMB;
#pragma unroll
        for (int ks = 0; ks < 4; ks++) {
            const int k = ks << 3;
            uint32_t af[2][4];
#pragma unroll
            for (int mi = 0; mi < 2; mi++) {
                const int r = wr * 32 + mi * 16 + g;
                af[mi][0] = __float_as_uint(A[r * 36 + k + tg]);
                af[mi][1] = __float_as_uint(A[(r + 8) * 36 + k + tg]);
                af[mi][2] = __float_as_uint(A[r * 36 + k + tg + 4]);
                af[mi][3] = __float_as_uint(A[(r + 8) * 36 + k + tg + 4]);
            }
            uint32_t bf[8][2];
#pragma unroll
            for (int ni = 0; ni < 8; ni++) {
                const int c = wc * 64 + ni * 8 + g;
                bf[ni][0] = __float_as_uint(Bp[(k + tg) * 136 + c]);
                bf[ni][1] = __float_as_uint(Bp[(k + tg + 4) * 136 + c]);
            }
#pragma unroll
            for (int mi = 0; mi < 2; mi++)
#pragma unroll
                for (int ni = 0; ni < 8; ni++)
                    mma8(acc[mi][ni], af[mi], bf[ni]);
        }
        __syncthreads();
    }

    // epilogue: bias + RoPE, write q/k in [B][T][S][D], tf32-rounded
#pragma unroll
    for (int mi = 0; mi < 2; mi++) {
        const int m0  = bM + wr * 32 + mi * 16 + g;  // global row (b*S + s)
        const int bi  = m0 >> 8;
        const int s0  = m0 & 255;
        const int s1  = s0 + 8;
#pragma unroll
        for (int ni = 0; ni < 8; ni++) {
            const int n  = bN + wc * 64 + ni * 8 + (tg << 1);  // even column
            const int t  = n >> 7;
            const int r  = n & 127;
            const int dd = r & 63;       // even dim within head half
            const int ii = dd >> 1;      // rope pair index
            const float bv0 = bias[n];
            const float bv1 = bias[n + 1];
            float* dst = (r < 64 ? g_q : g_k) +
                         (((size_t)bi * NT + t) * NS) * ND + dd;
            {
                float2 cs = g_rope[s0 * 32 + ii];
                float v0 = acc[mi][ni][0] + bv0;
                float v1 = acc[mi][ni][1] + bv1;
                float o0 = v0 * cs.x - v1 * cs.y;
                float o1 = v1 * cs.x + v0 * cs.y;
                *(float2*)(dst + (size_t)s0 * ND) = make_float2(tf32r(o0), tf32r(o1));
            }
            {
                float2 cs = g_rope[s1 * 32 + ii];
                float v0 = acc[mi][ni][2] + bv0;
                float v1 = acc[mi][ni][3] + bv1;
                float o0 = v0 * cs.x - v1 * cs.y;
                float o1 = v1 * cs.x + v0 * cs.y;
                *(float2*)(dst + (size_t)s1 * ND) = make_float2(tf32r(o0), tf32r(o1));
            }
        }
    }
}

// ---------------- kernel 2: logits[b,h] = Q @ K^T with mask epilogue ----------------
// grid (2, 2, B*T); block tile 128x128, K=64 staged once in smem.
// Qs/Ks: [128][68] (pad 4 -> conflict-free frag reads).
#define SMEM2 (2 * 128 * 68 * 4)

__global__ __launch_bounds__(256) void k_gemm2(const float* __restrict__ mask,
                                               float* __restrict__ out) {
    extern __shared__ float sm[];
    float* const Qs = sm;            // [128][68]
    float* const Ks = sm + 128 * 68;

    const int tid  = threadIdx.x;
    const int lane = tid & 31;
    const int warp = tid >> 5;
    const int g    = lane >> 2;
    const int tg   = lane & 3;
    const int wr   = warp & 3;
    const int wc   = warp >> 2;

    const int z  = blockIdx.z;        // b*T + h
    const int b  = z / NT;
    const int m0 = blockIdx.y << 7;
    const int n0 = blockIdx.x << 7;

    const float* Q = g_q + (size_t)z * NS * ND;
    const float* K = g_k + (size_t)z * NS * ND;

    {
        const int r0 = tid >> 4;          // 0..15
        const int c  = (tid & 15) << 2;   // 0..60
#pragma unroll
        for (int i = 0; i < 8; i++) {
            int r = r0 + i * 16;
            *(float4*)(Qs + r * 68 + c) = *(const float4*)(Q + (size_t)(m0 + r) * ND + c);
            *(float4*)(Ks + r * 68 + c) = *(const float4*)(K + (size_t)(n0 + r) * ND + c);
        }
    }
    __syncthreads();

    float acc[2][8][4];
#pragma unroll
    for (int i = 0; i < 2; i++)
#pragma unroll
        for (int j = 0; j < 8; j++)
#pragma unroll
            for (int l = 0; l < 4; l++) acc[i][j][l] = 0.f;

#pragma unroll
    for (int ks = 0; ks < 8; ks++) {
        const int k = ks << 3;
        uint32_t af[2][4];
#pragma unroll
        for (int mi = 0; mi < 2; mi++) {
            const int r = wr * 32 + mi * 16 + g;
            af[mi][0] = __float_as_uint(Qs[r * 68 + k + tg]);
            af[mi][1] = __float_as_uint(Qs[(r + 8) * 68 + k + tg]);
            af[mi][2] = __float_as_uint(Qs[r * 68 + k + tg + 4]);
            af[mi][3] = __float_as_uint(Qs[(r + 8) * 68 + k + tg + 4]);
        }
        uint32_t bf[8][2];
#pragma unroll
        for (int ni = 0; ni < 8; ni++) {
            const int c = wc * 64 + ni * 8 + g;
            bf[ni][0] = __float_as_uint(Ks[c * 68 + k + tg]);
            bf[ni][1] = __float_as_uint(Ks[c * 68 + k + tg + 4]);
        }
#pragma unroll
        for (int mi = 0; mi < 2; mi++)
#pragma unroll
            for (int ni = 0; ni < 8; ni++)
                mma8(acc[mi][ni], af[mi], bf[ni]);
    }

    // epilogue: pad mask, causal mask (m > n), scale 1/8
    const float rs = 0.125f;
#pragma unroll
    for (int mi = 0; mi < 2; mi++) {
        const int mrow = m0 + wr * 32 + mi * 16 + g;
#pragma unroll
        for (int ni = 0; ni < 8; ni++) {
            const int n = n0 + wc * 64 + ni * 8 + (tg << 1);
            const float p0 = mask[b * NS + n];
            const float p1 = mask[b * NS + n + 1];
            {
                float v0 = acc[mi][ni][0] * p0 - (1.0f - p0) * NEGC;
                float v1 = acc[mi][ni][1] * p1 - (1.0f - p1) * NEGC;
                if (mrow > n) v0 -= NEGC;
                if (mrow > n + 1) v1 -= NEGC;
                *(float2*)(out + ((size_t)z * NS + mrow) * NS + n) =
                    make_float2(v0 * rs, v1 * rs);
            }
            {
                const int mr2 = mrow + 8;
                float v0 = acc[mi][ni][2] * p0 - (1.0f - p0) * NEGC;
                float v1 = acc[mi][ni][3] * p1 - (1.0f - p1) * NEGC;
                if (mr2 > n) v0 -= NEGC;
                if (mr2 > n + 1) v1 -= NEGC;
                *(float2*)(out + ((size_t)z * NS + mr2) * NS + n) =
                    make_float2(v0 * rs, v1 * rs);
            }
        }
    }
}

// ---------------- launcher ----------------
extern "C" void kernel_launch(void* const* d_in, const int* in_sizes, int n_in,
                              void* d_out, int out_size) {
    const float* X    = (const float*)d_in[0];  // (B,S,H)
    const float* W    = (const float*)d_in[1];  // (H, T*2*D)
    const float* bias = (const float*)d_in[2];  // (T*2*D,)
    const float* mask = (const float*)d_in[3];  // (B,S)
    float* out = (float*)d_out;

    cudaFuncSetAttribute(k_gemm1, cudaFuncAttributeMaxDynamicSharedMemorySize, SMEM1);
    cudaFuncSetAttribute(k_gemm2, cudaFuncAttributeMaxDynamicSharedMemorySize, SMEM2);

    k_rope_tab<<<32, 256>>>();

    {
        size_t n4 = (size_t)NB * NS * NH / 4;
        k_cvt_x<<<(unsigned)((n4 + 255) / 256), 256>>>(X);
    }
    {
        size_t n4 = (size_t)NH * NN / 4;
        k_cvt_w<<<(unsigned)((n4 + 255) / 256), 256>>>(W);
    }

    k_gemm1<<<dim3(NN / 128, (NB * NS) / 128), 256, SMEM1>>>(bias);
    k_gemm2<<<dim3(2, 2, NB * NT), 256, SMEM2>>>(mask, out);
}

// round 16
// speedup vs baseline: 2.2716x; 2.2716x over previous
#include <cuda_runtime.h>
#include <cuda_bf16.h>
#include <cstdint>
#include <cstddef>

#define NB 64
#define NS 256
#define NH 768
#define NT 13
#define ND 64
#define NN (NT * 2 * ND)   // 1664
#define NEGC 1000000000000.0f

// ---------------- scratch (device globals) ----------------
__device__ __nv_bfloat16 g_xb[(size_t)NB * NS * NH];      // bf16 hidden [M][768]  (25.2 MB)
__device__ __nv_bfloat16 g_wb[(size_t)NN * NH];           // bf16 W^T   [n][k=768] (2.6 MB)
__device__ __nv_bfloat16 g_qb[(size_t)NB * NT * NS * ND]; // rotated q  [z][s][d]  (27.3 MB)
__device__ __nv_bfloat16 g_kb[(size_t)NB * NT * NS * ND]; // rotated k  [z][s][d]  (27.3 MB)
__device__ float2 g_rope[NS * 32];                        // (cos, sin) per (pos, pair)

// ---------------- helpers ----------------
__device__ __forceinline__ void cpa16(void* dst, const void* src) {
    uint32_t s = (uint32_t)__cvta_generic_to_shared(dst);
    asm volatile("cp.async.cg.shared.global [%0], [%1], 16;" :: "r"(s), "l"(src));
}
#define CP_COMMIT asm volatile("cp.async.commit_group;")
#define CP_WAIT1  asm volatile("cp.async.wait_group 1;")
#define CP_WAIT0  asm volatile("cp.async.wait_group 0;")

__device__ __forceinline__ void ldsm4(uint32_t& r0, uint32_t& r1, uint32_t& r2, uint32_t& r3,
                                      uint32_t addr) {
    asm volatile("ldmatrix.sync.aligned.m8n8.x4.shared.b16 {%0,%1,%2,%3}, [%4];"
                 : "=r"(r0), "=r"(r1), "=r"(r2), "=r"(r3) : "r"(addr));
}

__device__ __forceinline__ void mma16(float* c, const uint32_t* a, const uint32_t* b) {
    asm volatile(
        "mma.sync.aligned.m16n8k16.row.col.f32.bf16.bf16.f32 "
        "{%0,%1,%2,%3},{%4,%5,%6,%7},{%8,%9},{%0,%1,%2,%3};"
        : "+f"(c[0]), "+f"(c[1]), "+f"(c[2]), "+f"(c[3])
        : "r"(a[0]), "r"(a[1]), "r"(a[2]), "r"(a[3]), "r"(b[0]), "r"(b[1]));
}

// ---------------- prep kernels ----------------
__global__ void k_rope_tab() {
    int idx = blockIdx.x * blockDim.x + threadIdx.x;
    if (idx < NS * 32) {
        int s = idx >> 5, i = idx & 31;
        float inv = expf(-0.28782313662425574f * (float)i);  // 10000^(-i/32)
        float ang = (float)s * inv;
        g_rope[idx] = make_float2(cosf(ang), sinf(ang));
    }
}

// X fp32 -> bf16 (same layout). 8 elems per thread.
__global__ void k_cvt_x(const float* __restrict__ in) {
    size_t i = (size_t)blockIdx.x * blockDim.x + threadIdx.x;
    size_t n8 = (size_t)NB * NS * NH / 8;
    if (i < n8) {
        const float4* src = (const float4*)in + i * 2;
        float4 a = src[0], b = src[1];
        __nv_bfloat162 o[4];
        o[0] = __floats2bfloat162_rn(a.x, a.y);
        o[1] = __floats2bfloat162_rn(a.z, a.w);
        o[2] = __floats2bfloat162_rn(b.x, b.y);
        o[3] = __floats2bfloat162_rn(b.z, b.w);
        *(uint4*)(g_xb + i * 8) = *(uint4*)o;
    }
}

// W fp32 [k=768][n=1664] -> bf16 transposed [n][k]. Write coalesced along k.
__global__ void k_cvt_w(const float* __restrict__ in) {
    size_t i = (size_t)blockIdx.x * blockDim.x + threadIdx.x;  // over n*k
    size_t tot = (size_t)NN * NH;
    if (i < tot) {
        int n = (int)(i / NH);
        int k = (int)(i % NH);
        g_wb[i] = __float2bfloat16_rn(in[(size_t)k * NN + n]);
    }
}

// ---------------- kernel 1: X@W + bias, fused RoPE, bf16 q/k out ----------------
// BM=128, BN=128, BK=32 (bf16). 8 warps: 4 rows x 2 cols, warp tile 32x64.
// As: [128 m][40 k] bf16 (pad 8 -> 80B stride, LDSM conflict-free)
// Bs: [128 n][40 k] bf16 (W^T layout)
#define S1_STRIDE 40
#define S1_TILE   (128 * S1_STRIDE)          // elems per tile
#define S1_STAGE  (2 * S1_TILE)              // A+B elems per stage
#define SMEM1     (2 * S1_STAGE * 2)         // bytes (2 stages) = 40 KB

__global__ __launch_bounds__(256) void k_gemm1(const float* __restrict__ bias) {
    extern __shared__ __nv_bfloat16 sm[];
    const uint32_t sbase = (uint32_t)__cvta_generic_to_shared(sm);

    const int tid  = threadIdx.x;
    const int lane = tid & 31;
    const int warp = tid >> 5;
    const int g    = lane >> 2;
    const int tg   = lane & 3;
    const int wr   = warp & 3;
    const int wc   = warp >> 2;
    const int bM   = blockIdx.y << 7;
    const int bN   = blockIdx.x << 7;

    // cp.async mapping: 16B chunks, row has 4 chunks (32 bf16)
    const int crow = tid >> 2;          // 0..63
    const int ccol = (tid & 3) << 3;    // elem offset 0,8,16,24

    // ldmatrix lane addressing (byte addresses relative to tile start)
    const int l8  = lane & 7;
    const int sel = lane >> 3;
    uint32_t aoff[2];
#pragma unroll
    for (int mi = 0; mi < 2; mi++) {
        int r = wr * 32 + mi * 16 + (sel & 1) * 8 + l8;
        aoff[mi] = (uint32_t)((r * S1_STRIDE + (sel >> 1) * 8) * 2);
    }
    uint32_t boff[4];
#pragma unroll
    for (int nj = 0; nj < 4; nj++) {
        int r = wc * 64 + nj * 16 + (sel >> 1) * 8 + l8;
        boff[nj] = (uint32_t)((S1_TILE + r * S1_STRIDE + (sel & 1) * 8) * 2);
    }

    float acc[2][8][4];
#pragma unroll
    for (int i = 0; i < 2; i++)
#pragma unroll
        for (int j = 0; j < 8; j++)
#pragma unroll
            for (int l = 0; l < 4; l++) acc[i][j][l] = 0.f;

    // prologue: stage 0 <- kt 0
    {
#pragma unroll
        for (int i = 0; i < 2; i++) {
            int r = crow + i * 64;
            cpa16(sm + r * S1_STRIDE + ccol, g_xb + (size_t)(bM + r) * NH + ccol);
            cpa16(sm + S1_TILE + r * S1_STRIDE + ccol, g_wb + (size_t)(bN + r) * NH + ccol);
        }
        CP_COMMIT;
    }

    for (int kt = 0; kt < 24; kt++) {
        if (kt < 23) {
            const int st = (kt + 1) & 1;
            const int k0 = (kt + 1) << 5;
            __nv_bfloat16* dst = sm + st * S1_STAGE;
#pragma unroll
            for (int i = 0; i < 2; i++) {
                int r = crow + i * 64;
                cpa16(dst + r * S1_STRIDE + ccol, g_xb + (size_t)(bM + r) * NH + k0 + ccol);
                cpa16(dst + S1_TILE + r * S1_STRIDE + ccol,
                      g_wb + (size_t)(bN + r) * NH + k0 + ccol);
            }
        }
        CP_COMMIT;
        CP_WAIT1;
        __syncthreads();

        const uint32_t stg = sbase + (uint32_t)((kt & 1) * S1_STAGE * 2);
#pragma unroll
        for (int ks = 0; ks < 2; ks++) {
            const uint32_t kb = (uint32_t)(ks * 16 * 2);
            uint32_t af[2][4];
#pragma unroll
            for (int mi = 0; mi < 2; mi++)
                ldsm4(af[mi][0], af[mi][1], af[mi][2], af[mi][3], stg + aoff[mi] + kb);
            uint32_t bf[8][2];
#pragma unroll
            for (int nj = 0; nj < 4; nj++)
                ldsm4(bf[nj * 2][0], bf[nj * 2][1], bf[nj * 2 + 1][0], bf[nj * 2 + 1][1],
                      stg + boff[nj] + kb);
#pragma unroll
            for (int mi = 0; mi < 2; mi++)
#pragma unroll
                for (int ni = 0; ni < 8; ni++)
                    mma16(acc[mi][ni], af[mi], bf[ni]);
        }
        __syncthreads();
    }

    // epilogue: bias + RoPE, bf16 q/k in [z][s][d]
#pragma unroll
    for (int mi = 0; mi < 2; mi++) {
        const int m0 = bM + wr * 32 + mi * 16 + g;  // b*S + s
        const int bi = m0 >> 8;
        const int s0 = m0 & 255;
        const int s1 = s0 + 8;
#pragma unroll
        for (int ni = 0; ni < 8; ni++) {
            const int n  = bN + wc * 64 + ni * 8 + (tg << 1);
            const int t  = n >> 7;
            const int r  = n & 127;
            const int dd = r & 63;
            const int ii = dd >> 1;
            const float bv0 = bias[n];
            const float bv1 = bias[n + 1];
            __nv_bfloat16* dst = (r < 64 ? g_qb : g_kb) +
                                 ((size_t)(bi * NT + t) * NS) * ND + dd;
            {
                float2 cs = g_rope[s0 * 32 + ii];
                float v0 = acc[mi][ni][0] + bv0;
                float v1 = acc[mi][ni][1] + bv1;
                *(__nv_bfloat162*)(dst + (size_t)s0 * ND) =
                    __floats2bfloat162_rn(v0 * cs.x - v1 * cs.y, v1 * cs.x + v0 * cs.y);
            }
            {
                float2 cs = g_rope[s1 * 32 + ii];
                float v0 = acc[mi][ni][2] + bv0;
                float v1 = acc[mi][ni][3] + bv1;
                *(__nv_bfloat162*)(dst + (size_t)s1 * ND) =
                    __floats2bfloat162_rn(v0 * cs.x - v1 * cs.y, v1 * cs.x + v0 * cs.y);
            }
        }
    }
}

// ---------------- kernel 2: logits = Q @ K^T + mask, bf16 MMA ----------------
// grid (2,2,B*T); 128x128 tile, K=64 staged once. Qs/Ks: [128][72] bf16.
#define S2_STRIDE 72
#define S2_TILE   (128 * S2_STRIDE)
#define SMEM2     (2 * S2_TILE * 2)   // 36 KB

__global__ __launch_bounds__(256) void k_gemm2(const float* __restrict__ mask,
                                               float* __restrict__ out) {
    extern __shared__ __nv_bfloat16 sm[];
    const uint32_t sbase = (uint32_t)__cvta_generic_to_shared(sm);

    const int tid  = threadIdx.x;
    const int lane = tid & 31;
    const int warp = tid >> 5;
    const int g    = lane >> 2;
    const int tg   = lane & 3;
    const int wr   = warp & 3;
    const int wc   = warp >> 2;

    const int z  = blockIdx.z;   // b*T + h
    const int b  = z / NT;
    const int m0 = blockIdx.y << 7;
    const int n0 = blockIdx.x << 7;

    const __nv_bfloat16* Q = g_qb + (size_t)z * NS * ND;
    const __nv_bfloat16* K = g_kb + (size_t)z * NS * ND;

    {
        const int row = tid >> 3;        // 0..31
        const int col = (tid & 7) << 3;  // elem 0..56
#pragma unroll
        for (int i = 0; i < 4; i++) {
            int r = row + i * 32;
            cpa16(sm + r * S2_STRIDE + col, Q + (size_t)(m0 + r) * ND + col);
            cpa16(sm + S2_TILE + r * S2_STRIDE + col, K + (size_t)(n0 + r) * ND + col);
        }
        CP_COMMIT;
        CP_WAIT0;
        __syncthreads();
    }

    const int l8  = lane & 7;
    const int sel = lane >> 3;
    uint32_t aoff[2];
#pragma unroll
    for (int mi = 0; mi < 2; mi++) {
        int r = wr * 32 + mi * 16 + (sel & 1) * 8 + l8;
        aoff[mi] = sbase + (uint32_t)((r * S2_STRIDE + (sel >> 1) * 8) * 2);
    }
    uint32_t boff[4];
#pragma unroll
    for (int nj = 0; nj < 4; nj++) {
        int r = wc * 64 + nj * 16 + (sel >> 1) * 8 + l8;
        boff[nj] = sbase + (uint32_t)((S2_TILE + r * S2_STRIDE + (sel & 1) * 8) * 2);
    }

    float acc[2][8][4];
#pragma unroll
    for (int i = 0; i < 2; i++)
#pragma unroll
        for (int j = 0; j < 8; j++)
#pragma unroll
            for (int l = 0; l < 4; l++) acc[i][j][l] = 0.f;

#pragma unroll
    for (int ks = 0; ks < 4; ks++) {
        const uint32_t kb = (uint32_t)(ks * 16 * 2);
        uint32_t af[2][4];
#pragma unroll
        for (int mi = 0; mi < 2; mi++)
            ldsm4(af[mi][0], af[mi][1], af[mi][2], af[mi][3], aoff[mi] + kb);
        uint32_t bf[8][2];
#pragma unroll
        for (int nj = 0; nj < 4; nj++)
            ldsm4(bf[nj * 2][0], bf[nj * 2][1], bf[nj * 2 + 1][0], bf[nj * 2 + 1][1],
                  boff[nj] + kb);
#pragma unroll
        for (int mi = 0; mi < 2; mi++)
#pragma unroll
            for (int ni = 0; ni < 8; ni++)
                mma16(acc[mi][ni], af[mi], bf[ni]);
    }

    // epilogue: pad mask, causal (m > n), scale 1/8
    const float rs = 0.125f;
#pragma unroll
    for (int mi = 0; mi < 2; mi++) {
        const int mrow = m0 + wr * 32 + mi * 16 + g;
#pragma unroll
        for (int ni = 0; ni < 8; ni++) {
            const int n = n0 + wc * 64 + ni * 8 + (tg << 1);
            const float p0 = mask[b * NS + n];
            const float p1 = mask[b * NS + n + 1];
            {
                float v0 = acc[mi][ni][0] * p0 - (1.0f - p0) * NEGC;
                float v1 = acc[mi][ni][1] * p1 - (1.0f - p1) * NEGC;
                if (mrow > n) v0 -= NEGC;
                if (mrow > n + 1) v1 -= NEGC;
                *(float2*)(out + ((size_t)z * NS + mrow) * NS + n) =
                    make_float2(v0 * rs, v1 * rs);
            }
            {
                const int mr2 = mrow + 8;
                float v0 = acc[mi][ni][2] * p0 - (1.0f - p0) * NEGC;
                float v1 = acc[mi][ni][3] * p1 - (1.0f - p1) * NEGC;
                if (mr2 > n) v0 -= NEGC;
                if (mr2 > n + 1) v1 -= NEGC;
                *(float2*)(out + ((size_t)z * NS + mr2) * NS + n) =
                    make_float2(v0 * rs, v1 * rs);
            }
        }
    }
}

// ---------------- launcher ----------------
extern "C" void kernel_launch(void* const* d_in, const int* in_sizes, int n_in,
                              void* d_out, int out_size) {
    const float* X    = (const float*)d_in[0];  // (B,S,H)
    const float* W    = (const float*)d_in[1];  // (H, T*2*D)
    const float* bias = (const float*)d_in[2];  // (T*2*D,)
    const float* mask = (const float*)d_in[3];  // (B,S)
    float* out = (float*)d_out;

    k_rope_tab<<<32, 256>>>();
    {
        size_t n8 = (size_t)NB * NS * NH / 8;
        k_cvt_x<<<(unsigned)((n8 + 255) / 256), 256>>>(X);
    }
    {
        size_t tot = (size_t)NN * NH;
        k_cvt_w<<<(unsigned)((tot + 255) / 256), 256>>>(W);
    }

    k_gemm1<<<dim3(NN / 128, (NB * NS) / 128), 256, SMEM1>>>(bias);
    k_gemm2<<<dim3(2, 2, NB * NT), 256, SMEM2>>>(mask, out);
}